// round 6
// baseline (speedup 1.0000x reference)
#include <cuda_runtime.h>
#include <cstdint>

#define B_  32
#define T_  2048
#define D_  256
#define H_  256
#define A_  18
#define G4  1024
#define M_  (B_*T_)          // 65536

#define LOGITS_OFF 0
#define LAST_OFF   ((size_t)M_*A_)                   // 1179648
#define C_OFF      (LAST_OFF + (size_t)M_*H_)        // 17956864
#define HF_OFF     (C_OFF + (size_t)B_*H_)           // 17965056

// 256 MB scratch for pre-computed input gates (x @ Wx + b)
__device__ float g_scr[(size_t)M_ * G4];

// ---------------- f32x2 packed helpers ----------------
__device__ __forceinline__ unsigned long long pk2(float lo, float hi){
    unsigned long long r;
    asm("mov.b64 %0, {%1,%2};" : "=l"(r) : "f"(lo), "f"(hi));
    return r;
}
__device__ __forceinline__ void fma2(unsigned long long &d, unsigned long long a, unsigned long long b){
    asm("fma.rn.f32x2 %0, %1, %2, %0;" : "+l"(d) : "l"(a), "l"(b));
}
__device__ __forceinline__ unsigned long long add2_(unsigned long long a, unsigned long long b){
    unsigned long long r;
    asm("add.rn.f32x2 %0, %1, %2;" : "=l"(r) : "l"(a), "l"(b));
    return r;
}
__device__ __forceinline__ float2 up2(unsigned long long v){
    float2 f;
    asm("mov.b64 {%0,%1}, %2;" : "=f"(f.x), "=f"(f.y) : "l"(v));
    return f;
}

__device__ __forceinline__ float sigf(float x){
    return 1.0f / (1.0f + __expf(-x));
}
__device__ __forceinline__ float tanh_fast(float x){
    return 1.0f - 2.0f / (1.0f + __expf(2.0f * x));
}

// ---------------- mbarrier / DSMEM helpers ----------------
__device__ __forceinline__ void mbar_init(unsigned int a, unsigned int cnt){
    asm volatile("mbarrier.init.shared.b64 [%0], %1;" :: "r"(a), "r"(cnt) : "memory");
}
__device__ __forceinline__ void mbar_expect(unsigned int a, unsigned int tx){
    asm volatile("mbarrier.arrive.expect_tx.shared.b64 _, [%0], %1;" :: "r"(a), "r"(tx) : "memory");
}
__device__ __forceinline__ void mbar_wait(unsigned int a, unsigned int par){
    asm volatile(
        "{\n\t.reg .pred P;\n"
        "LAB_%=:\n\t"
        "mbarrier.try_wait.parity.acquire.cta.shared::cta.b64 P, [%0], %1, 0x989680;\n\t"
        "@P bra DONE_%=;\n\t"
        "bra LAB_%=;\n"
        "DONE_%=:\n\t}"
        :: "r"(a), "r"(par) : "memory");
}
__device__ __forceinline__ unsigned int mapa_(unsigned int a, unsigned int r){
    unsigned int d;
    asm("mapa.shared::cluster.u32 %0, %1, %2;" : "=r"(d) : "r"(a), "r"(r));
    return d;
}
// bulk smem->peer-smem copy; complete_tx fires at the (remote) mbarrier
__device__ __forceinline__ void bulk_s2s(unsigned int dst, unsigned int src,
                                         unsigned int n, unsigned int mbar){
    asm volatile(
        "cp.async.bulk.shared::cluster.shared::cta.mbarrier::complete_tx::bytes [%0], [%1], %2, [%3];"
        :: "r"(dst), "r"(src), "r"(n), "r"(mbar) : "memory");
}
__device__ __forceinline__ void fence_proxy_async_(){
    asm volatile("fence.proxy.async.shared::cta;" ::: "memory");
}
__device__ __forceinline__ void cluster_sync_(){
    asm volatile("barrier.cluster.arrive.aligned;" ::: "memory");
    asm volatile("barrier.cluster.wait.aligned;"   ::: "memory");
}

// ======================================================================
// Kernel 1: pre-GEMM  G[m][c] = x[m,:] @ W[0:256, c] + b[c]
// BM=128, BN=128, BK=16, 256 threads, thread tile 8x8 (two 4-col halves)
// ======================================================================
#define PG_BM 128
#define PG_BN 128
#define PG_BK 16

__global__ __launch_bounds__(256,2) void pregemm_k(
    const float* __restrict__ x, const float* __restrict__ W,
    const float* __restrict__ bias)
{
    __shared__ float a_s[PG_BK][PG_BM];
    __shared__ float b_s[PG_BK][PG_BN];

    int tid = threadIdx.x;
    int m0 = blockIdx.y * PG_BM;
    int n0 = blockIdx.x * PG_BN;
    int tx = tid & 15;           // col group: cols tx*4 and 64+tx*4
    int ty = tid >> 4;           // row group: rows ty*8..+7

    unsigned long long acc[8][4];
#pragma unroll
    for (int i = 0; i < 8; i++)
#pragma unroll
        for (int j = 0; j < 4; j++) acc[i][j] = 0ull;

    for (int k0 = 0; k0 < D_; k0 += PG_BK){
        // A tile: 128 rows x 16 k = 512 float4, 2 per thread
#pragma unroll
        for (int i = 0; i < 2; i++){
            int f4 = tid*2 + i;
            int m  = f4 >> 2;
            int kq = f4 & 3;
            float4 v = *(const float4*)&x[(size_t)(m0+m)*D_ + k0 + kq*4];
            a_s[kq*4+0][m] = v.x; a_s[kq*4+1][m] = v.y;
            a_s[kq*4+2][m] = v.z; a_s[kq*4+3][m] = v.w;
        }
        // B tile: 16 rows x 128 cols = 512 float4, 2 per thread
#pragma unroll
        for (int i = 0; i < 2; i++){
            int f4 = tid*2 + i;
            int row = f4 >> 5, cq = f4 & 31;
            float4 v = *(const float4*)&W[(size_t)(k0+row)*G4 + n0 + cq*4];
            *(float4*)&b_s[row][cq*4] = v;
        }
        __syncthreads();
#pragma unroll
        for (int kk = 0; kk < PG_BK; kk++){
            float4 a0 = *(float4*)&a_s[kk][ty*8];
            float4 a1 = *(float4*)&a_s[kk][ty*8+4];
            float4 b0 = *(float4*)&b_s[kk][tx*4];
            float4 b1 = *(float4*)&b_s[kk][64 + tx*4];
            unsigned long long bp0 = pk2(b0.x,b0.y), bp1 = pk2(b0.z,b0.w);
            unsigned long long bp2 = pk2(b1.x,b1.y), bp3 = pk2(b1.z,b1.w);
            float ar[8] = {a0.x,a0.y,a0.z,a0.w,a1.x,a1.y,a1.z,a1.w};
#pragma unroll
            for (int i = 0; i < 8; i++){
                unsigned long long ap = pk2(ar[i], ar[i]);
                fma2(acc[i][0], ap, bp0);
                fma2(acc[i][1], ap, bp1);
                fma2(acc[i][2], ap, bp2);
                fma2(acc[i][3], ap, bp3);
            }
        }
        __syncthreads();
    }

    float4 bv0 = *(const float4*)&bias[n0 + tx*4];
    float4 bv1 = *(const float4*)&bias[n0 + 64 + tx*4];
#pragma unroll
    for (int i = 0; i < 8; i++){
        float2 l0 = up2(acc[i][0]), h0 = up2(acc[i][1]);
        float2 l1 = up2(acc[i][2]), h1 = up2(acc[i][3]);
        size_t row = (size_t)(m0 + ty*8 + i)*G4;
        *(float4*)&g_scr[row + n0 + tx*4] =
            make_float4(l0.x+bv0.x, l0.y+bv0.y, h0.x+bv0.z, h0.y+bv0.w);
        *(float4*)&g_scr[row + n0 + 64 + tx*4] =
            make_float4(l1.x+bv1.x, l1.y+bv1.y, h1.x+bv1.z, h1.y+bv1.w);
    }
}

// ======================================================================
// Kernel 2: recurrent LSTM.
// 16 clusters x 8 CTAs. Cluster = 2 batches. CTA = 32 units.
// 256 threads = 8 warps; warp = 4 units (u_lo) x 8 k-chunks (kq).
// Weights 100% register-resident; shuffle-butterfly gate reduction.
// h exchange: per-CTA staging tile -> ONE cp.async.bulk (256 B) per peer
// per step, complete_tx at the peer mbarrier (8 arrivals/step, not 256).
// ======================================================================
#define HRANK 68                 // floats per rank slot: 64 data + 4 pad
#define PHASE_B (8*HRANK*4)      // 2176 bytes per phase
#define SLOT_B  (HRANK*4)        // 272 bytes per rank slot

__global__ __launch_bounds__(256,1) __cluster_dims__(8,1,1)
void lstm_rec_k(const float* __restrict__ W, const int* __restrict__ seq_lens,
                const float* __restrict__ c_in, const float* __restrict__ h_in,
                float* __restrict__ out)
{
    // h_s[phase][rank][batch*32 + u_local]; rank stride 68 floats (272 B)
    __shared__ __align__(16) float h_s[2][8][HRANK];
    __shared__ __align__(16) float stage[2][64];     // [dest phase][b*32+u_local]
    __shared__ __align__(8) unsigned long long barr[2];

    int tid  = threadIdx.x;
    int warp = tid >> 5, lane = tid & 31;
    int rank = blockIdx.x & 7, cl = blockIdx.x >> 3;
    int u_lo = lane >> 3;           // 0..3
    int kq   = lane & 7;            // 0..7  (k-chunk / reduction lane)
    int b_c  = kq >> 2;             // this lane's combo batch
    int g_c  = kq & 3;              // this lane's combo gate
    int u    = rank*32 + warp*4 + u_lo;     // global unit 0..255
    int bg_c = cl*2 + b_c;                  // combo's global batch
    int gcol_c = g_c*256 + u;               // combo's global gate column

    // --- weights: 4 gates x 32 k (chunk kq) in 64 u64 registers ---
    const float* Wh = W + (size_t)D_*G4;
    unsigned long long wreg[4][16];
#pragma unroll
    for (int g = 0; g < 4; g++){
        int gc = g*256 + u;
#pragma unroll
        for (int j = 0; j < 16; j++){
            int k = kq*32 + 2*j;
            wreg[g][j] = pk2(Wh[(size_t)k*G4 + gc], Wh[(size_t)(k+1)*G4 + gc]);
        }
    }

    unsigned int hsm     = (unsigned int)__cvta_generic_to_shared(&h_s[0][0][0]);
    unsigned int st_addr = (unsigned int)__cvta_generic_to_shared(&stage[0][0]);
    unsigned int bar_lo  = (unsigned int)__cvta_generic_to_shared(&barr[0]);

    unsigned int base_r[8], barr_r[8];
#pragma unroll
    for (int r = 0; r < 8; r++){
        base_r[r] = mapa_(hsm, (unsigned)r);
        barr_r[r] = mapa_(bar_lo, (unsigned)r);
    }
    unsigned int myslot = (unsigned)rank * SLOT_B;   // offset within a phase

    if (tid == 0){
        mbar_init(bar_lo,     1);
        mbar_init(bar_lo + 8, 1);
        mbar_expect(bar_lo,     2048);   // init copies (phase-0 buffer)
        mbar_expect(bar_lo + 8, 2048);   // step-0 sends (phase-1 buffer)
    }

    // writers: g_c == 0 lanes own combo (b_c, unit u)
    bool is_wr  = (g_c == 0);
    bool is_wr2 = is_wr && ((u_lo & 1) == 0);
    float c_r = 0.f, h_r = 0.f; int slen = 0;
    if (is_wr){
        c_r  = c_in[(size_t)bg_c*H_ + u];
        h_r  = h_in[(size_t)bg_c*H_ + u];
        slen = seq_lens[bg_c];
    }

    // --- init: fill stage[0] with this CTA's h slice and broadcast ---
    if (tid < 64){
        int b = tid >> 5, ul = tid & 31;
        stage[0][tid] = h_in[(size_t)(cl*2 + b)*H_ + rank*32 + ul];
    }
    __syncthreads();
    cluster_sync_();   // peers' barriers armed before any bulk copy
    if (tid == 0){
        fence_proxy_async_();
#pragma unroll
        for (int r = 0; r < 8; r++)
            bulk_s2s(base_r[r] + myslot, st_addr, 256, barr_r[r]);
    }

    float pre = g_scr[((size_t)bg_c*T_ + 0)*G4 + gcol_c];

    for (int t = 0; t < T_; t++){
        int p   = t & 1;
        int par = (t >> 1) & 1;
        mbar_wait(bar_lo + p*8, (unsigned)par);
        if (tid == 0) mbar_expect(bar_lo + p*8, 2048);   // re-arm for t+2

        // prefetch next step's pre-gate
        int tn = (t+1 < T_) ? t+1 : t;
        float pre_n = g_scr[((size_t)bg_c*T_ + tn)*G4 + gcol_c];

        // --- gemm: acc[g][b] over this thread's 32-k chunk (rank slot kq) ---
        const ulonglong2* h0 = (const ulonglong2*)&h_s[p][kq][0];
        const ulonglong2* h1 = (const ulonglong2*)&h_s[p][kq][32];
        unsigned long long acc[4][2];
#pragma unroll
        for (int g = 0; g < 4; g++){ acc[g][0] = 0ull; acc[g][1] = 0ull; }
#pragma unroll
        for (int q = 0; q < 8; q++){
            ulonglong2 hb0 = h0[q];
            ulonglong2 hb1 = h1[q];
#pragma unroll
            for (int g = 0; g < 4; g++){
                fma2(acc[g][0], wreg[g][2*q  ], hb0.x);
                fma2(acc[g][0], wreg[g][2*q+1], hb0.y);
                fma2(acc[g][1], wreg[g][2*q  ], hb1.x);
                fma2(acc[g][1], wreg[g][2*q+1], hb1.y);
            }
        }

        // --- butterfly reduce over kq; lane ends with combo (b_c, g_c) ---
        unsigned long long acck[4];
#pragma unroll
        for (int g = 0; g < 4; g++){
            unsigned long long send = acc[g][b_c ^ 1];
            unsigned long long got  = __shfl_xor_sync(0xffffffffu, send, 4);
            acck[g] = add2_(acc[g][b_c], got);
        }
        int gh = (kq >> 1) & 1;
        unsigned long long s0 = acck[2*(gh^1)    ];
        unsigned long long s1 = acck[2*(gh^1) + 1];
        unsigned long long r0 = __shfl_xor_sync(0xffffffffu, s0, 2);
        unsigned long long r1 = __shfl_xor_sync(0xffffffffu, s1, 2);
        unsigned long long accg0 = add2_(acck[2*gh    ], r0);
        unsigned long long accg1 = add2_(acck[2*gh + 1], r1);
        int gl = kq & 1;
        unsigned long long s2 = gl ? accg0 : accg1;
        unsigned long long r2 = __shfl_xor_sync(0xffffffffu, s2, 1);
        unsigned long long fin = add2_(gl ? accg1 : accg0, r2);
        float2 fv = up2(fin);
        float s_val = fv.x + fv.y + pre;     // pre lands on its own combo lane

        // --- gather 4 gates for (u_lo, b_c) ---
        int base = (lane & 24) | (b_c << 2);
        float gi = __shfl_sync(0xffffffffu, s_val, base + 0);
        float gj = __shfl_sync(0xffffffffu, s_val, base + 1);
        float gf = __shfl_sync(0xffffffffu, s_val, base + 2);
        float go = __shfl_sync(0xffffffffu, s_val, base + 3);

        // --- activation (meaningful on writer lanes) ---
        float sf = sigf(gf + 1.0f);
        float si = sigf(gi);
        float tj = tanh_fast(gj);
        float so = sigf(go);
        float nc = c_r * sf + si * tj;
        float nh = tanh_fast(nc) * so;
        bool mask = (t < slen);
        if (mask){ c_r = nc; h_r = nh; }
        float oval = mask ? nh : 0.f;

        // --- emit: output pair + staging store ---
        float o_hi = __shfl_down_sync(0xffffffffu, oval, 8);
        if (is_wr2)
            *(float2*)&out[LAST_OFF + ((size_t)bg_c*T_ + t)*H_ + u] =
                make_float2(oval, o_hi);
        if (is_wr)
            stage[p^1][b_c*32 + warp*4 + u_lo] = h_r;
        __syncthreads();   // staging complete before bulk copy reads it

        if (tid == 0 && t + 1 < T_){
            fence_proxy_async_();
            unsigned int so  = st_addr + (unsigned)(p^1)*256;
            unsigned int doff = myslot + (unsigned)(p^1)*PHASE_B;
            unsigned int boff = (unsigned)(p^1)*8;
#pragma unroll
            for (int r = 0; r < 8; r++)
                bulk_s2s(base_r[r] + doff, so, 256, barr_r[r] + boff);
        }
        pre = pre_n;
    }

    if (is_wr){
        out[C_OFF  + (size_t)bg_c*H_ + u] = c_r;
        out[HF_OFF + (size_t)bg_c*H_ + u] = h_r;
    }
    cluster_sync_();   // no CTA exits while peers may still target its smem
}

// ======================================================================
// Kernel 3: logits = last_layer @ W_out + b_out   [65536,256]@[256,18]
// block = 14 rows x 18 outputs = 252 threads
// ======================================================================
#define WO_ST 260

__global__ __launch_bounds__(252) void logits_k(
    const float* __restrict__ Wout, const float* __restrict__ bout,
    float* __restrict__ out)
{
    __shared__ float wo[A_*WO_ST];
    __shared__ float bo[A_];
    int tid = threadIdx.x;
    for (int i = tid; i < H_*A_; i += 252){
        int k = i / A_, a = i % A_;
        wo[a*WO_ST + k] = Wout[(size_t)k*A_ + a];
    }
    if (tid < A_) bo[tid] = bout[tid];
    __syncthreads();

    int r = blockIdx.x*14 + tid/A_;
    int a = tid % A_;
    if (r >= M_) return;
    const float* hrow = out + LAST_OFF + (size_t)r*H_;
    const float* wa = wo + a*WO_ST;
    unsigned long long acc = 0ull;
#pragma unroll
    for (int k4 = 0; k4 < H_/4; k4++){
        float4 hv = *(const float4*)&hrow[k4*4];
        float4 wv = *(const float4*)&wa[k4*4];
        fma2(acc, pk2(hv.x,hv.y), pk2(wv.x,wv.y));
        fma2(acc, pk2(hv.z,hv.w), pk2(wv.z,wv.w));
    }
    float2 s = up2(acc);
    out[(size_t)r*A_ + a] = s.x + s.y + bo[a];
}

// ======================================================================
extern "C" void kernel_launch(void* const* d_in, const int* in_sizes, int n_in,
                              void* d_out, int out_size)
{
    const float* x     = (const float*)d_in[0];
    const int*   seq   = (const int*)  d_in[1];
    const float* c_in  = (const float*)d_in[2];
    const float* h_in  = (const float*)d_in[3];
    const float* W     = (const float*)d_in[4];
    const float* b     = (const float*)d_in[5];
    const float* Wout  = (const float*)d_in[6];
    const float* bout  = (const float*)d_in[7];
    float* out = (float*)d_out;

    pregemm_k<<<dim3(G4/PG_BN, M_/PG_BM), 256>>>(x, W, b);
    lstm_rec_k<<<128, 256>>>(W, seq, c_in, h_in, out);
    logits_k<<<(M_ + 13)/14, 252>>>(Wout, bout, out);
}

// round 7
// speedup vs baseline: 1.2421x; 1.2421x over previous
#include <cuda_runtime.h>
#include <cstdint>

#define B_  32
#define T_  2048
#define D_  256
#define H_  256
#define A_  18
#define G4  1024
#define M_  (B_*T_)          // 65536

#define LOGITS_OFF 0
#define LAST_OFF   ((size_t)M_*A_)                   // 1179648
#define C_OFF      (LAST_OFF + (size_t)M_*H_)        // 17956864
#define HF_OFF     (C_OFF + (size_t)B_*H_)           // 17965056

// 256 MB scratch for pre-computed input gates (x @ Wx + b)
__device__ float g_scr[(size_t)M_ * G4];

// ---------------- f32x2 packed helpers ----------------
__device__ __forceinline__ unsigned long long pk2(float lo, float hi){
    unsigned long long r;
    asm("mov.b64 %0, {%1,%2};" : "=l"(r) : "f"(lo), "f"(hi));
    return r;
}
__device__ __forceinline__ void fma2(unsigned long long &d, unsigned long long a, unsigned long long b){
    asm("fma.rn.f32x2 %0, %1, %2, %0;" : "+l"(d) : "l"(a), "l"(b));
}
__device__ __forceinline__ float2 up2(unsigned long long v){
    float2 f;
    asm("mov.b64 {%0,%1}, %2;" : "=f"(f.x), "=f"(f.y) : "l"(v));
    return f;
}

__device__ __forceinline__ float sigf(float x){
    return 1.0f / (1.0f + __expf(-x));
}
__device__ __forceinline__ float tanh_fast(float x){
    return 1.0f - 2.0f / (1.0f + __expf(2.0f * x));
}

// ---------------- mbarrier / DSMEM helpers ----------------
__device__ __forceinline__ void mbar_init(unsigned int a, unsigned int cnt){
    asm volatile("mbarrier.init.shared.b64 [%0], %1;" :: "r"(a), "r"(cnt) : "memory");
}
__device__ __forceinline__ void mbar_expect(unsigned int a, unsigned int tx){
    asm volatile("mbarrier.arrive.expect_tx.shared.b64 _, [%0], %1;" :: "r"(a), "r"(tx) : "memory");
}
// CTA-scope acquire: DSMEM-delivered smem data needs no global ordering.
__device__ __forceinline__ void mbar_wait(unsigned int a, unsigned int par){
    asm volatile(
        "{\n\t.reg .pred P;\n"
        "LAB_%=:\n\t"
        "mbarrier.try_wait.parity.acquire.cta.shared::cta.b64 P, [%0], %1, 0x989680;\n\t"
        "@P bra DONE_%=;\n\t"
        "bra LAB_%=;\n"
        "DONE_%=:\n\t}"
        :: "r"(a), "r"(par) : "memory");
}
__device__ __forceinline__ unsigned int mapa_(unsigned int a, unsigned int r){
    unsigned int d;
    asm("mapa.shared::cluster.u32 %0, %1, %2;" : "=r"(d) : "r"(a), "r"(r));
    return d;
}
__device__ __forceinline__ void st_async64(unsigned int dst, unsigned long long v, unsigned int mbar){
    asm volatile("st.async.weak.shared::cluster.mbarrier::complete_tx::bytes.b64 [%0], %1, [%2];"
                 :: "r"(dst), "l"(v), "r"(mbar) : "memory");
}
__device__ __forceinline__ void cluster_sync_(){
    asm volatile("barrier.cluster.arrive.aligned;" ::: "memory");
    asm volatile("barrier.cluster.wait.aligned;"   ::: "memory");
}

// ======================================================================
// Kernel 1: pre-GEMM  G[m][c] = x[m,:] @ W[0:256, c] + b[c]
// ======================================================================
#define PG_BM 128
#define PG_BN 128
#define PG_BK 16

__global__ __launch_bounds__(256,2) void pregemm_k(
    const float* __restrict__ x, const float* __restrict__ W,
    const float* __restrict__ bias)
{
    __shared__ float a_s[PG_BK][PG_BM];
    __shared__ float b_s[PG_BK][PG_BN];

    int tid = threadIdx.x;
    int m0 = blockIdx.y * PG_BM;
    int n0 = blockIdx.x * PG_BN;
    int tx = tid & 15;
    int ty = tid >> 4;

    unsigned long long acc[8][4];
#pragma unroll
    for (int i = 0; i < 8; i++)
#pragma unroll
        for (int j = 0; j < 4; j++) acc[i][j] = 0ull;

    for (int k0 = 0; k0 < D_; k0 += PG_BK){
#pragma unroll
        for (int i = 0; i < 2; i++){
            int f4 = tid*2 + i;
            int m  = f4 >> 2;
            int kq = f4 & 3;
            float4 v = *(const float4*)&x[(size_t)(m0+m)*D_ + k0 + kq*4];
            a_s[kq*4+0][m] = v.x; a_s[kq*4+1][m] = v.y;
            a_s[kq*4+2][m] = v.z; a_s[kq*4+3][m] = v.w;
        }
#pragma unroll
        for (int i = 0; i < 2; i++){
            int f4 = tid*2 + i;
            int row = f4 >> 5, cq = f4 & 31;
            float4 v = *(const float4*)&W[(size_t)(k0+row)*G4 + n0 + cq*4];
            *(float4*)&b_s[row][cq*4] = v;
        }
        __syncthreads();
#pragma unroll
        for (int kk = 0; kk < PG_BK; kk++){
            float4 a0 = *(float4*)&a_s[kk][ty*8];
            float4 a1 = *(float4*)&a_s[kk][ty*8+4];
            float4 b0 = *(float4*)&b_s[kk][tx*4];
            float4 b1 = *(float4*)&b_s[kk][64 + tx*4];
            unsigned long long bp0 = pk2(b0.x,b0.y), bp1 = pk2(b0.z,b0.w);
            unsigned long long bp2 = pk2(b1.x,b1.y), bp3 = pk2(b1.z,b1.w);
            float ar[8] = {a0.x,a0.y,a0.z,a0.w,a1.x,a1.y,a1.z,a1.w};
#pragma unroll
            for (int i = 0; i < 8; i++){
                unsigned long long ap = pk2(ar[i], ar[i]);
                fma2(acc[i][0], ap, bp0);
                fma2(acc[i][1], ap, bp1);
                fma2(acc[i][2], ap, bp2);
                fma2(acc[i][3], ap, bp3);
            }
        }
        __syncthreads();
    }

    float4 bv0 = *(const float4*)&bias[n0 + tx*4];
    float4 bv1 = *(const float4*)&bias[n0 + 64 + tx*4];
#pragma unroll
    for (int i = 0; i < 8; i++){
        float2 l0 = up2(acc[i][0]), h0 = up2(acc[i][1]);
        float2 l1 = up2(acc[i][2]), h1 = up2(acc[i][3]);
        size_t row = (size_t)(m0 + ty*8 + i)*G4;
        *(float4*)&g_scr[row + n0 + tx*4] =
            make_float4(l0.x+bv0.x, l0.y+bv0.y, h0.x+bv0.z, h0.y+bv0.w);
        *(float4*)&g_scr[row + n0 + 64 + tx*4] =
            make_float4(l1.x+bv1.x, l1.y+bv1.y, h1.x+bv1.z, h1.y+bv1.w);
    }
}

// ======================================================================
// Kernel 2: recurrent LSTM.
// 16 clusters x 8 CTAs, cluster = 2 batches, CTA = 32 units, 256 thr.
// Warp = 4 units (u_lo) x 8 k-chunks (kq); weights register-resident.
// f32 butterfly reduce; h exchange via st.async spread over ALL lanes
// (1 message per lane per step); mbarrier waits are CTA-scope acquire.
// ======================================================================
#define HRANK  68                 // floats per rank slot: 64 data + 4 pad
#define SLOT_B (HRANK*4)          // 272 B
#define PHASE_B (8*SLOT_B)        // 2176 B

__global__ __launch_bounds__(256,1) __cluster_dims__(8,1,1)
void lstm_rec_k(const float* __restrict__ W, const int* __restrict__ seq_lens,
                const float* __restrict__ c_in, const float* __restrict__ h_in,
                float* __restrict__ out)
{
    // h_s[phase][src rank][batch*32 + unit_local]
    __shared__ __align__(16) float h_s[2][8][HRANK];
    __shared__ __align__(8) unsigned long long barr[2];

    int tid  = threadIdx.x;
    int warp = tid >> 5, lane = tid & 31;
    int rank = blockIdx.x & 7, cl = blockIdx.x >> 3;
    int u_lo = lane >> 3;           // 0..3
    int kq   = lane & 7;            // 0..7
    int b_c  = kq >> 2;             // combo batch
    int g_c  = kq & 3;              // combo gate
    int u    = rank*32 + warp*4 + u_lo;
    int bg_c = cl*2 + b_c;
    int gcol_c = g_c*256 + u;

    // --- weights: 4 gates x 32 k (chunk kq) in 64 u64 registers ---
    const float* Wh = W + (size_t)D_*G4;
    unsigned long long wreg[4][16];
#pragma unroll
    for (int g = 0; g < 4; g++){
        int gc = g*256 + u;
#pragma unroll
        for (int j = 0; j < 16; j++){
            int k = kq*32 + 2*j;
            wreg[g][j] = pk2(Wh[(size_t)k*G4 + gc], Wh[(size_t)(k+1)*G4 + gc]);
        }
    }

    unsigned int hsm    = (unsigned int)__cvta_generic_to_shared(&h_s[0][0][0]);
    unsigned int bar_lo = (unsigned int)__cvta_generic_to_shared(&barr[0]);

    // this lane's send role: dest rank + which (batch, unit-pair)
    int r_dst = lane & 7;
    int sel   = lane >> 3;          // 0..3
    int b_s   = sel & 1;
    int ph    = sel >> 1;           // unit pair within warp's 4 units
    unsigned int dst_base = mapa_(hsm, (unsigned)r_dst)
                          + (unsigned)rank*SLOT_B
                          + (unsigned)((b_s*32 + warp*4 + ph*2)*4);
    unsigned int dst_bar  = mapa_(bar_lo, (unsigned)r_dst);
    int src_lo = ph*16 + b_s*4;     // lane holding h_r for unit 2ph (this batch)

    if (tid == 0){
        mbar_init(bar_lo,     1);
        mbar_init(bar_lo + 8, 1);
        mbar_expect(bar_lo,     2048);   // init broadcast (phase 0)
        mbar_expect(bar_lo + 8, 2048);   // step-0 sends (phase 1)
    }

    // writers: g_c == 0 lanes own state of (b_c, unit u)
    bool is_wr  = (g_c == 0);
    bool is_wr2 = is_wr && ((u_lo & 1) == 0);
    float c_r = 0.f, h_r = 0.f; int slen = 0;
    if (is_wr){
        c_r  = c_in[(size_t)bg_c*H_ + u];
        h_r  = h_in[(size_t)bg_c*H_ + u];
        slen = seq_lens[bg_c];
    }

    __syncthreads();
    cluster_sync_();   // barriers armed cluster-wide before any st.async

    // --- initial h broadcast into phase-0 buffer (all lanes, 1 msg each) ---
    {
        float v_lo = __shfl_sync(0xffffffffu, h_r, src_lo);
        float v_hi = __shfl_sync(0xffffffffu, h_r, src_lo + 8);
        st_async64(dst_base, pk2(v_lo, v_hi), dst_bar);
    }

    float pre = g_scr[((size_t)bg_c*T_ + 0)*G4 + gcol_c];

    for (int t = 0; t < T_; t++){
        int p   = t & 1;
        int par = (t >> 1) & 1;
        mbar_wait(bar_lo + p*8, (unsigned)par);
        if (tid == 0) mbar_expect(bar_lo + p*8, 2048);   // re-arm for t+2

        int tn = (t+1 < T_) ? t+1 : t;
        float pre_n = g_scr[((size_t)bg_c*T_ + tn)*G4 + gcol_c];

        // --- gemm: acc[g][b] over this thread's 32-k chunk (rank slot kq) ---
        const ulonglong2* h0 = (const ulonglong2*)&h_s[p][kq][0];
        const ulonglong2* h1 = (const ulonglong2*)&h_s[p][kq][32];
        unsigned long long acc[4][2];
#pragma unroll
        for (int g = 0; g < 4; g++){ acc[g][0] = 0ull; acc[g][1] = 0ull; }
#pragma unroll
        for (int q = 0; q < 8; q++){
            ulonglong2 hb0 = h0[q];
            ulonglong2 hb1 = h1[q];
#pragma unroll
            for (int g = 0; g < 4; g++){
                fma2(acc[g][0], wreg[g][2*q  ], hb0.x);
                fma2(acc[g][0], wreg[g][2*q+1], hb0.y);
                fma2(acc[g][1], wreg[g][2*q  ], hb1.x);
                fma2(acc[g][1], wreg[g][2*q+1], hb1.y);
            }
        }

        // --- collapse to f32, then 3-level butterfly over kq ---
        float s[4][2];
#pragma unroll
        for (int g = 0; g < 4; g++){
            float2 f0 = up2(acc[g][0]); s[g][0] = f0.x + f0.y;
            float2 f1 = up2(acc[g][1]); s[g][1] = f1.x + f1.y;
        }
        float a0 = s[0][b_c] + __shfl_xor_sync(0xffffffffu, s[0][b_c^1], 4);
        float a1 = s[1][b_c] + __shfl_xor_sync(0xffffffffu, s[1][b_c^1], 4);
        float a2 = s[2][b_c] + __shfl_xor_sync(0xffffffffu, s[2][b_c^1], 4);
        float a3 = s[3][b_c] + __shfl_xor_sync(0xffffffffu, s[3][b_c^1], 4);
        int gh = (kq >> 1) & 1;
        float k0 = gh ? a2 : a0, k1 = gh ? a3 : a1;      // keep pair
        float x0 = gh ? a0 : a2, x1 = gh ? a1 : a3;      // send pair
        float m0 = k0 + __shfl_xor_sync(0xffffffffu, x0, 2);
        float m1 = k1 + __shfl_xor_sync(0xffffffffu, x1, 2);
        int gl = kq & 1;
        float keep = gl ? m1 : m0;
        float send = gl ? m0 : m1;
        float s_val = keep + __shfl_xor_sync(0xffffffffu, send, 1) + pre;

        // --- gather 4 gates for (u_lo, b_c) ---
        int base = (lane & 24) | (b_c << 2);
        float gi = __shfl_sync(0xffffffffu, s_val, base + 0);
        float gj = __shfl_sync(0xffffffffu, s_val, base + 1);
        float gf = __shfl_sync(0xffffffffu, s_val, base + 2);
        float go = __shfl_sync(0xffffffffu, s_val, base + 3);

        // --- activation (meaningful on writer lanes) ---
        float sf = sigf(gf + 1.0f);
        float si = sigf(gi);
        float tj = tanh_fast(gj);
        float so = sigf(go);
        float nc = c_r * sf + si * tj;
        float nh = tanh_fast(nc) * so;
        bool mask = (t < slen);
        if (mask){ c_r = nc; h_r = nh; }
        float oval = mask ? nh : 0.f;

        // --- sends FIRST (critical path): every lane ships one pair ---
        float v_lo = __shfl_sync(0xffffffffu, h_r, src_lo);
        float v_hi = __shfl_sync(0xffffffffu, h_r, src_lo + 8);
        if (t + 1 < T_)
            st_async64(dst_base + (unsigned)(p^1)*PHASE_B, pk2(v_lo, v_hi),
                       dst_bar + (unsigned)(p^1)*8);

        // --- output store (off critical path) ---
        float o_hi = __shfl_down_sync(0xffffffffu, oval, 8);
        if (is_wr2)
            *(float2*)&out[LAST_OFF + ((size_t)bg_c*T_ + t)*H_ + u] =
                make_float2(oval, o_hi);

        pre = pre_n;
    }

    if (is_wr){
        out[C_OFF  + (size_t)bg_c*H_ + u] = c_r;
        out[HF_OFF + (size_t)bg_c*H_ + u] = h_r;
    }
    cluster_sync_();   // no CTA exits while peers may still target its smem
}

// ======================================================================
// Kernel 3: logits = last_layer @ W_out + b_out   [65536,256]@[256,18]
// ======================================================================
#define WO_ST 260

__global__ __launch_bounds__(252) void logits_k(
    const float* __restrict__ Wout, const float* __restrict__ bout,
    float* __restrict__ out)
{
    __shared__ float wo[A_*WO_ST];
    __shared__ float bo[A_];
    int tid = threadIdx.x;
    for (int i = tid; i < H_*A_; i += 252){
        int k = i / A_, a = i % A_;
        wo[a*WO_ST + k] = Wout[(size_t)k*A_ + a];
    }
    if (tid < A_) bo[tid] = bout[tid];
    __syncthreads();

    int r = blockIdx.x*14 + tid/A_;
    int a = tid % A_;
    if (r >= M_) return;
    const float* hrow = out + LAST_OFF + (size_t)r*H_;
    const float* wa = wo + a*WO_ST;
    unsigned long long acc = 0ull;
#pragma unroll
    for (int k4 = 0; k4 < H_/4; k4++){
        float4 hv = *(const float4*)&hrow[k4*4];
        float4 wv = *(const float4*)&wa[k4*4];
        fma2(acc, pk2(hv.x,hv.y), pk2(wv.x,wv.y));
        fma2(acc, pk2(hv.z,hv.w), pk2(wv.z,wv.w));
    }
    float2 s = up2(acc);
    out[(size_t)r*A_ + a] = s.x + s.y + bo[a];
}

// ======================================================================
extern "C" void kernel_launch(void* const* d_in, const int* in_sizes, int n_in,
                              void* d_out, int out_size)
{
    const float* x     = (const float*)d_in[0];
    const int*   seq   = (const int*)  d_in[1];
    const float* c_in  = (const float*)d_in[2];
    const float* h_in  = (const float*)d_in[3];
    const float* W     = (const float*)d_in[4];
    const float* b     = (const float*)d_in[5];
    const float* Wout  = (const float*)d_in[6];
    const float* bout  = (const float*)d_in[7];
    float* out = (float*)d_out;

    pregemm_k<<<dim3(G4/PG_BN, M_/PG_BM), 256>>>(x, W, b);
    lstm_rec_k<<<128, 256>>>(W, seq, c_in, h_in, out);
    logits_k<<<(M_ + 13)/14, 252>>>(Wout, bout, out);
}